// round 7
// baseline (speedup 1.0000x reference)
#include <cuda_runtime.h>
#include <cuda_bf16.h>
#include <cstdint>

#define N_NODES 50000
#define N_EDGES 800000
#define HID 64
#define N_CLS 16
#define MAX_DEG 64

// Scratch (device globals — no allocation allowed)
__device__ int   g_cnt[N_NODES];
__device__ int   g_adj[N_NODES * MAX_DEG];
__device__ __align__(16) float g_mean[N_NODES * HID];   // mean of x[src] per dst
__device__ __align__(16) float g_h[N_NODES * HID];      // layer-1 output
__device__ __align__(16) float g_p[N_NODES * N_CLS];    // h @ W2_l
__device__ __align__(16) float g_pm[N_NODES * N_CLS];   // mean of p[src] per dst

// ---- packed f32x2 helpers (Blackwell FFMA2) --------------------------------
__device__ __forceinline__ unsigned long long pk(float a, float b) {
    unsigned long long r;
    asm("mov.b64 %0, {%1, %2};" : "=l"(r) : "f"(a), "f"(b));
    return r;
}
__device__ __forceinline__ void fma2(unsigned long long& d,
                                     unsigned long long a, unsigned long long b) {
    asm("fma.rn.f32x2 %0, %1, %2, %0;" : "+l"(d) : "l"(a), "l"(b));
}
__device__ __forceinline__ float2 upk(unsigned long long v) {
    float2 f;
    asm("mov.b64 {%0, %1}, %2;" : "=f"(f.x), "=f"(f.y) : "l"(v));
    return f;
}

// ---------------------------------------------------------------------------
__global__ void zero_cnt_k() {
    int i = blockIdx.x * blockDim.x + threadIdx.x;
    if (i < N_NODES) g_cnt[i] = 0;
}

__global__ void fill_k(const int* __restrict__ ei) {
    int e = blockIdx.x * blockDim.x + threadIdx.x;
    if (e >= N_EDGES) return;
    int s = ei[e];
    int d = ei[N_EDGES + e];
    if ((unsigned)s >= N_NODES || (unsigned)d >= N_NODES) return;
    int pos = atomicAdd(&g_cnt[d], 1);
    if (pos < MAX_DEG) g_adj[d * MAX_DEG + pos] = s;
}

// ---------------------------------------------------------------------------
// High-MLP mean gather: thread = (node, float4-chunk).
// SEL: 0 -> src = x (input arg), dst = g_mean, W4=16
//      1 -> src = g_p,           dst = g_pm,   W4=4
// ---------------------------------------------------------------------------
template<int SEL, int LOG_W4>
__global__ void gather_mean_k(const float4* __restrict__ xin) {
    constexpr int W4 = 1 << LOG_W4;
    const float4* src = (SEL == 0) ? xin : reinterpret_cast<const float4*>(g_p);
    float4* dst = (SEL == 0) ? reinterpret_cast<float4*>(g_mean)
                             : reinterpret_cast<float4*>(g_pm);
    int t = blockIdx.x * blockDim.x + threadIdx.x;
    int node = t >> LOG_W4;
    int f = t & (W4 - 1);
    if (node >= N_NODES) return;
    int c = g_cnt[node];
    int cl = min(c, MAX_DEG);
    const int4* row4 = reinterpret_cast<const int4*>(g_adj + (size_t)node * MAX_DEG);
    float4 a0 = make_float4(0.f,0.f,0.f,0.f), a1 = a0, a2 = a0, a3 = a0;
    int nfull = cl >> 2;
#pragma unroll 2
    for (int j4 = 0; j4 < nfull; j4++) {
        int4 idx = __ldg(row4 + j4);
        float4 v0 = __ldg(src + (((size_t)idx.x) << LOG_W4) + f);
        float4 v1 = __ldg(src + (((size_t)idx.y) << LOG_W4) + f);
        float4 v2 = __ldg(src + (((size_t)idx.z) << LOG_W4) + f);
        float4 v3 = __ldg(src + (((size_t)idx.w) << LOG_W4) + f);
        a0.x += v0.x; a0.y += v0.y; a0.z += v0.z; a0.w += v0.w;
        a1.x += v1.x; a1.y += v1.y; a1.z += v1.z; a1.w += v1.w;
        a2.x += v2.x; a2.y += v2.y; a2.z += v2.z; a2.w += v2.w;
        a3.x += v3.x; a3.y += v3.y; a3.z += v3.z; a3.w += v3.w;
    }
    for (int j = nfull * 4; j < cl; j++) {
        int s = __ldg(g_adj + (size_t)node * MAX_DEG + j);
        float4 v = __ldg(src + (((size_t)s) << LOG_W4) + f);
        a0.x += v.x; a0.y += v.y; a0.z += v.z; a0.w += v.w;
    }
    float invd = 1.0f / fmaxf((float)c, 1.0f);
    float4 r;
    r.x = (a0.x + a1.x + a2.x + a3.x) * invd;
    r.y = (a0.y + a1.y + a2.y + a3.y) * invd;
    r.z = (a0.z + a1.z + a2.z + a3.z) * invd;
    r.w = (a0.w + a1.w + a2.w + a3.w) * invd;
    dst[((size_t)node << LOG_W4) + f] = r;
}

// ---------------------------------------------------------------------------
// Layer 1 GEMM (packed f32x2): h = relu(mean @ W1_l + x @ W1_r + b1); p = h @ W2_l
// 128 threads = 4 warps; q=8 nodes/warp (R5 config). Weight LDS as .128.
// ---------------------------------------------------------------------------
__global__ void __launch_bounds__(128)
layer1_k(const float* __restrict__ x,
         const float* __restrict__ W1l,
         const float* __restrict__ b1,
         const float* __restrict__ W1r,
         const float* __restrict__ W2l) {
    __shared__ float4 sW4[64][32];          // (wl_c, wr_c, wl_c+32, wr_c+32)  32KB
    __shared__ float  sW2t[16][64];         // W2l transposed [c][k]            4KB
    __shared__ float  sb1[64];
    __shared__ float2 sMX[4][8][64];        // (mean, x) per (warp,q,k)        16KB

    int tid = threadIdx.x, warp = tid >> 5, lane = tid & 31;
    for (int i = tid; i < 2048; i += 128) {
        int k = i >> 5, c = i & 31;
        sW4[k][c] = make_float4(W1l[k * 64 + c],      W1r[k * 64 + c],
                                W1l[k * 64 + c + 32], W1r[k * 64 + c + 32]);
    }
    for (int i = tid; i < 1024; i += 128) {
        int k = i >> 4, c = i & 15;
        sW2t[c][k] = W2l[i];
    }
    if (tid < 64) sb1[tid] = b1[tid];
    __syncthreads();

    for (int nb0 = blockIdx.x * 32; nb0 < N_NODES; nb0 += gridDim.x * 32) {
        int nb = nb0 + warp * 8;

        // stage (mean, x) for 8 nodes
#pragma unroll
        for (int q = 0; q < 8; q++) {
            int node = nb + q;
            if (node < N_NODES) {
                size_t r = (size_t)node * 64;
                sMX[warp][q][lane]      = make_float2(g_mean[r + lane],      x[r + lane]);
                sMX[warp][q][lane + 32] = make_float2(g_mean[r + lane + 32], x[r + lane + 32]);
            } else {
                sMX[warp][q][lane]      = make_float2(0.f, 0.f);
                sMX[warp][q][lane + 32] = make_float2(0.f, 0.f);
            }
        }
        __syncwarp();

        unsigned long long accA[8], accB[8];
#pragma unroll
        for (int q = 0; q < 8; q++) { accA[q] = pk(0.f, 0.f); accB[q] = pk(0.f, 0.f); }

#pragma unroll 4
        for (int k2 = 0; k2 < 32; k2++) {
            int k = k2 * 2;
            float4 w0 = sW4[k][lane];
            float4 w1 = sW4[k + 1][lane];
            unsigned long long WA0 = pk(w0.x, w0.y), WB0 = pk(w0.z, w0.w);
            unsigned long long WA1 = pk(w1.x, w1.y), WB1 = pk(w1.z, w1.w);
#pragma unroll
            for (int q = 0; q < 8; q++) {
                float4 mx = *reinterpret_cast<const float4*>(&sMX[warp][q][k]);
                unsigned long long m0 = pk(mx.x, mx.y);
                unsigned long long m1 = pk(mx.z, mx.w);
                fma2(accA[q], m0, WA0);
                fma2(accB[q], m0, WB0);
                fma2(accA[q], m1, WA1);
                fma2(accB[q], m1, WB1);
            }
        }
        __syncwarp();   // done reading sMX before h overwrites it

        // epilogue: h = relu(sum + bias); write g_h and stash h rows in sMX space
#pragma unroll
        for (int q = 0; q < 8; q++) {
            int node = nb + q;
            if (node < N_NODES) {
                float2 A = upk(accA[q]);
                float2 B = upk(accB[q]);
                float h0 = fmaxf(A.x + A.y + sb1[lane], 0.f);
                float h1 = fmaxf(B.x + B.y + sb1[lane + 32], 0.f);
                size_t r = (size_t)node * 64;
                g_h[r + lane]      = h0;
                g_h[r + lane + 32] = h1;
                float* sH = reinterpret_cast<float*>(&sMX[warp][q][0]);
                sH[lane]      = h0;
                sH[lane + 32] = h1;
            }
        }
        __syncwarp();

        {   // p = h @ W2_l : lane -> (node = lane>>2 in 0..7, cols c0..c0+3)
            int n = lane >> 2, c0 = (lane & 3) * 4;
            int node = nb + n;
            if (node < N_NODES) {
                const float* hrow = reinterpret_cast<const float*>(&sMX[warp][n][0]);
                unsigned long long Pa = pk(0.f,0.f), Pb = Pa, Pc = Pa, Pd = Pa;
#pragma unroll
                for (int k4 = 0; k4 < 16; k4++) {
                    int k = k4 * 4;
                    float4 hv = *reinterpret_cast<const float4*>(&hrow[k]);
                    unsigned long long h01 = pk(hv.x, hv.y);
                    unsigned long long h23 = pk(hv.z, hv.w);
                    float4 wA = *reinterpret_cast<const float4*>(&sW2t[c0 + 0][k]);
                    float4 wB = *reinterpret_cast<const float4*>(&sW2t[c0 + 1][k]);
                    float4 wC = *reinterpret_cast<const float4*>(&sW2t[c0 + 2][k]);
                    float4 wD = *reinterpret_cast<const float4*>(&sW2t[c0 + 3][k]);
                    fma2(Pa, h01, pk(wA.x, wA.y)); fma2(Pa, h23, pk(wA.z, wA.w));
                    fma2(Pb, h01, pk(wB.x, wB.y)); fma2(Pb, h23, pk(wB.z, wB.w));
                    fma2(Pc, h01, pk(wC.x, wC.y)); fma2(Pc, h23, pk(wC.z, wC.w));
                    fma2(Pd, h01, pk(wD.x, wD.y)); fma2(Pd, h23, pk(wD.z, wD.w));
                }
                float2 a = upk(Pa), b = upk(Pb), c = upk(Pc), d = upk(Pd);
                *reinterpret_cast<float4*>(g_p + (size_t)node * 16 + c0) =
                    make_float4(a.x + a.y, b.x + b.y, c.x + c.y, d.x + d.y);
            }
        }
        __syncwarp();   // p-proj done reading sH before next restage
    }
}

// ---------------------------------------------------------------------------
// Final: out = g_pm + h @ W2_r + b2  (k-pair packed, W2r transposed)
// Block = 128 = 4 warps; warp handles 4 nodes; lane -> (node=lane>>3, 2 cols)
// ---------------------------------------------------------------------------
__global__ void __launch_bounds__(128)
final_k(const float* __restrict__ W2r,
        const float* __restrict__ b2,
        float* __restrict__ out) {
    __shared__ float sWt[16][64];     // W2r transposed [c][k]
    __shared__ float sb[16];
    __shared__ float sh[4][4][64];
    int tid = threadIdx.x, warp = tid >> 5, lane = tid & 31;
    for (int i = tid; i < 1024; i += 128) {
        int k = i >> 4, c = i & 15;
        sWt[c][k] = W2r[i];
    }
    if (tid < 16) sb[tid] = b2[tid];
    __syncthreads();

    int n = lane >> 3, c0 = (lane & 7) * 2;
    for (int nb = (blockIdx.x * 4 + warp) * 4; nb < N_NODES; nb += gridDim.x * 16) {
        int nvalid = min(4, N_NODES - nb);
        for (int q = 0; q < nvalid; q++) {
            size_t r = (size_t)(nb + q) * 64;
            sh[warp][q][lane]      = g_h[r + lane];
            sh[warp][q][lane + 32] = g_h[r + lane + 32];
        }
        __syncwarp();
        if (n < nvalid) {
            int node = nb + n;
            unsigned long long P0 = pk(0.f, 0.f), P1 = pk(0.f, 0.f);
#pragma unroll
            for (int k4 = 0; k4 < 16; k4++) {
                int k = k4 * 4;
                float4 hv = *reinterpret_cast<const float4*>(&sh[warp][n][k]);
                unsigned long long h01 = pk(hv.x, hv.y);
                unsigned long long h23 = pk(hv.z, hv.w);
                float4 wA = *reinterpret_cast<const float4*>(&sWt[c0][k]);
                float4 wB = *reinterpret_cast<const float4*>(&sWt[c0 + 1][k]);
                fma2(P0, h01, pk(wA.x, wA.y)); fma2(P0, h23, pk(wA.z, wA.w));
                fma2(P1, h01, pk(wB.x, wB.y)); fma2(P1, h23, pk(wB.z, wB.w));
            }
            float2 pm = *reinterpret_cast<const float2*>(g_pm + (size_t)node * 16 + c0);
            float2 s0 = upk(P0), s1 = upk(P1);
            out[(size_t)node * 16 + c0]     = sb[c0]     + pm.x + s0.x + s0.y;
            out[(size_t)node * 16 + c0 + 1] = sb[c0 + 1] + pm.y + s1.x + s1.y;
        }
        __syncwarp();
    }
}

// ---------------------------------------------------------------------------
extern "C" void kernel_launch(void* const* d_in, const int* in_sizes, int n_in,
                              void* d_out, int out_size) {
    const float* x   = (const float*)d_in[0];
    const int*   ei  = (const int*)d_in[1];     // int32 (JAX x64 disabled)
    const float* W1l = (const float*)d_in[2];
    const float* b1  = (const float*)d_in[3];
    const float* W1r = (const float*)d_in[4];
    const float* W2l = (const float*)d_in[5];
    const float* b2  = (const float*)d_in[6];
    const float* W2r = (const float*)d_in[7];
    float* out = (float*)d_out;

    zero_cnt_k<<<(N_NODES + 255) / 256, 256>>>();
    fill_k<<<(N_EDGES + 255) / 256, 256>>>(ei);
    gather_mean_k<0, 4><<<(N_NODES * 16 + 255) / 256, 256>>>((const float4*)x);
    layer1_k<<<592, 128>>>(x, W1l, b1, W1r, W2l);
    gather_mean_k<1, 2><<<(N_NODES * 4 + 255) / 256, 256>>>(nullptr);
    final_k<<<592, 128>>>(W2r, b2, out);
}

// round 8
// speedup vs baseline: 1.7700x; 1.7700x over previous
#include <cuda_runtime.h>
#include <mma.h>
#include <cstdint>

using namespace nvcuda;

#define N_NODES 50000
#define N_PAD   50048            // padded to 64-row multiple for direct wmma I/O
#define N_EDGES 800000
#define HID 64
#define N_CLS 16
#define MAX_DEG 64

// Scratch (device globals — no allocation allowed)
__device__ int   g_cnt[N_NODES];
__device__ int   g_adj[N_NODES * MAX_DEG];
__device__ __align__(16) float g_mean[N_NODES * HID];   // mean of x[src] per dst
__device__ __align__(16) float g_h[N_PAD * HID];        // layer-1 output (padded)
__device__ __align__(16) float g_p[N_PAD * N_CLS];      // h @ W2_l (padded)
__device__ __align__(16) float g_pm[N_NODES * N_CLS];   // mean of p[src] per dst

// ---------------------------------------------------------------------------
__global__ void zero_cnt_k() {
    int i = blockIdx.x * blockDim.x + threadIdx.x;
    if (i < N_NODES) g_cnt[i] = 0;
}

__global__ void fill_k(const int* __restrict__ ei) {
    int e = blockIdx.x * blockDim.x + threadIdx.x;
    if (e >= N_EDGES) return;
    int s = ei[e];
    int d = ei[N_EDGES + e];
    if ((unsigned)s >= N_NODES || (unsigned)d >= N_NODES) return;
    int pos = atomicAdd(&g_cnt[d], 1);
    if (pos < MAX_DEG) g_adj[d * MAX_DEG + pos] = s;
}

// ---------------------------------------------------------------------------
// High-MLP mean gather (unchanged from R5): thread = (node, float4-chunk).
// SEL: 0 -> src = x (input arg), dst = g_mean, W4=16
//      1 -> src = g_p,           dst = g_pm,   W4=4
// ---------------------------------------------------------------------------
template<int SEL, int LOG_W4>
__global__ void gather_mean_k(const float4* __restrict__ xin) {
    constexpr int W4 = 1 << LOG_W4;
    const float4* src = (SEL == 0) ? xin : reinterpret_cast<const float4*>(g_p);
    float4* dst = (SEL == 0) ? reinterpret_cast<float4*>(g_mean)
                             : reinterpret_cast<float4*>(g_pm);
    int t = blockIdx.x * blockDim.x + threadIdx.x;
    int node = t >> LOG_W4;
    int f = t & (W4 - 1);
    if (node >= N_NODES) return;
    int c = g_cnt[node];
    int cl = min(c, MAX_DEG);
    const int4* row4 = reinterpret_cast<const int4*>(g_adj + (size_t)node * MAX_DEG);
    float4 a0 = make_float4(0.f,0.f,0.f,0.f), a1 = a0, a2 = a0, a3 = a0;
    int nfull = cl >> 2;
#pragma unroll 2
    for (int j4 = 0; j4 < nfull; j4++) {
        int4 idx = __ldg(row4 + j4);
        float4 v0 = __ldg(src + (((size_t)idx.x) << LOG_W4) + f);
        float4 v1 = __ldg(src + (((size_t)idx.y) << LOG_W4) + f);
        float4 v2 = __ldg(src + (((size_t)idx.z) << LOG_W4) + f);
        float4 v3 = __ldg(src + (((size_t)idx.w) << LOG_W4) + f);
        a0.x += v0.x; a0.y += v0.y; a0.z += v0.z; a0.w += v0.w;
        a1.x += v1.x; a1.y += v1.y; a1.z += v1.z; a1.w += v1.w;
        a2.x += v2.x; a2.y += v2.y; a2.z += v2.z; a2.w += v2.w;
        a3.x += v3.x; a3.y += v3.y; a3.z += v3.z; a3.w += v3.w;
    }
    for (int j = nfull * 4; j < cl; j++) {
        int s = __ldg(g_adj + (size_t)node * MAX_DEG + j);
        float4 v = __ldg(src + (((size_t)s) << LOG_W4) + f);
        a0.x += v.x; a0.y += v.y; a0.z += v.z; a0.w += v.w;
    }
    float invd = 1.0f / fmaxf((float)c, 1.0f);
    float4 r;
    r.x = (a0.x + a1.x + a2.x + a3.x) * invd;
    r.y = (a0.y + a1.y + a2.y + a3.y) * invd;
    r.z = (a0.z + a1.z + a2.z + a3.z) * invd;
    r.w = (a0.w + a1.w + a2.w + a3.w) * invd;
    dst[((size_t)node << LOG_W4) + f] = r;
}

// ---------------------------------------------------------------------------
template<class Frag>
__device__ __forceinline__ void cvt_tf32(Frag& f) {
#pragma unroll
    for (int i = 0; i < f.num_elements; i++) f.x[i] = wmma::__float_to_tf32(f.x[i]);
}

// ---------------------------------------------------------------------------
// Layer 1 via tf32 WMMA:
//   h = relu([mean||x] @ [W1l;W1r] + b1);  p = h @ W2_l
// Block = 128 threads = 4 warps; block handles 64 nodes; warp = 16 rows.
// A staged in smem (guarded). B fragments loaded directly from global (L1).
// ---------------------------------------------------------------------------
__global__ void __launch_bounds__(128)
layer1_k(const float* __restrict__ x,
         const float* __restrict__ W1l,
         const float* __restrict__ b1,
         const float* __restrict__ W1r,
         const float* __restrict__ W2l) {
    __shared__ float sA[64][132];   // [mean||x] rows, later h rows; 33.8KB
    __shared__ float sb1[64];

    int tid = threadIdx.x, warp = tid >> 5, lane = tid & 31;
    int node0 = blockIdx.x * 64;
    if (tid < 64) sb1[tid] = b1[tid];

    // Stage A = [mean || x], zero-filled past N_NODES
    const float4* m4 = reinterpret_cast<const float4*>(g_mean);
    const float4* x4 = reinterpret_cast<const float4*>(x);
    for (int i = tid; i < 2048; i += 128) {
        int r = i >> 5, c4 = i & 31;            // 32 float4 per 128-float row
        int node = node0 + r;
        float4 v = make_float4(0.f, 0.f, 0.f, 0.f);
        if (node < N_NODES)
            v = (c4 < 16) ? m4[(size_t)node * 16 + c4]
                          : x4[(size_t)node * 16 + (c4 - 16)];
        *reinterpret_cast<float4*>(&sA[r][c4 * 4]) = v;
    }
    __syncthreads();

    int m0 = warp * 16;

    // Main GEMM: acc[n] = A(16x128) @ B(128x16n-tile)
    wmma::fragment<wmma::accumulator, 16, 16, 8, float> acc[4];
#pragma unroll
    for (int n = 0; n < 4; n++) wmma::fill_fragment(acc[n], 0.f);

#pragma unroll
    for (int k = 0; k < 128; k += 8) {
        wmma::fragment<wmma::matrix_a, 16, 16, 8, wmma::precision::tf32, wmma::row_major> a;
        wmma::load_matrix_sync(a, &sA[m0][k], 132);
        cvt_tf32(a);
        const float* Bk = (k < 64) ? (W1l + (size_t)k * 64)
                                   : (W1r + (size_t)(k - 64) * 64);
#pragma unroll
        for (int n = 0; n < 4; n++) {
            wmma::fragment<wmma::matrix_b, 16, 16, 8, wmma::precision::tf32, wmma::row_major> b;
            wmma::load_matrix_sync(b, Bk + n * 16, 64);
            cvt_tf32(b);
            wmma::mma_sync(acc[n], a, b, acc[n]);
        }
    }

    // Store raw sums into this warp's own rows (cols 0..63) — no cross-warp hazard
#pragma unroll
    for (int n = 0; n < 4; n++)
        wmma::store_matrix_sync(&sA[m0][n * 16], acc[n], 132, wmma::mem_row_major);
    __syncwarp();

    // Bias + relu in smem; write g_h (guarded)
    for (int i = lane; i < 16 * 64; i += 32) {
        int r = i >> 6, c = i & 63;
        float v = fmaxf(sA[m0 + r][c] + sb1[c], 0.f);
        sA[m0 + r][c] = v;
        int node = node0 + m0 + r;
        if (node < N_NODES) g_h[(size_t)node * 64 + c] = v;
    }
    __syncwarp();

    // p = h @ W2_l, direct store into padded g_p
    wmma::fragment<wmma::accumulator, 16, 16, 8, float> acc2;
    wmma::fill_fragment(acc2, 0.f);
#pragma unroll
    for (int k = 0; k < 64; k += 8) {
        wmma::fragment<wmma::matrix_a, 16, 16, 8, wmma::precision::tf32, wmma::row_major> a2;
        wmma::load_matrix_sync(a2, &sA[m0][k], 132);
        cvt_tf32(a2);
        wmma::fragment<wmma::matrix_b, 16, 16, 8, wmma::precision::tf32, wmma::row_major> b2;
        wmma::load_matrix_sync(b2, W2l + (size_t)k * 16, 16);
        cvt_tf32(b2);
        wmma::mma_sync(acc2, a2, b2, acc2);
    }
    wmma::store_matrix_sync(g_p + (size_t)(node0 + m0) * 16, acc2, 16, wmma::mem_row_major);
}

// ---------------------------------------------------------------------------
// Final via tf32 WMMA: out = g_pm + h @ W2_r + b2
// a-fragments loaded directly from padded g_h; no staging.
// ---------------------------------------------------------------------------
__global__ void __launch_bounds__(128)
final_k(const float* __restrict__ W2r,
        const float* __restrict__ b2,
        float* __restrict__ out) {
    __shared__ float sO[64][16];
    __shared__ float sb[16];
    int tid = threadIdx.x, warp = tid >> 5, lane = tid & 31;
    int node0 = blockIdx.x * 64;
    if (tid < 16) sb[tid] = b2[tid];
    __syncthreads();

    int m0 = warp * 16;
    wmma::fragment<wmma::accumulator, 16, 16, 8, float> acc;
    wmma::fill_fragment(acc, 0.f);
#pragma unroll
    for (int k = 0; k < 64; k += 8) {
        wmma::fragment<wmma::matrix_a, 16, 16, 8, wmma::precision::tf32, wmma::row_major> a;
        wmma::load_matrix_sync(a, g_h + (size_t)(node0 + m0) * 64 + k, 64);
        cvt_tf32(a);
        wmma::fragment<wmma::matrix_b, 16, 16, 8, wmma::precision::tf32, wmma::row_major> b;
        wmma::load_matrix_sync(b, W2r + (size_t)k * 16, 16);
        cvt_tf32(b);
        wmma::mma_sync(acc, a, b, acc);
    }
    wmma::store_matrix_sync(&sO[m0][0], acc, 16, wmma::mem_row_major);
    __syncwarp();

    for (int i = lane; i < 16 * 16; i += 32) {
        int r = i >> 4, c = i & 15;
        int node = node0 + m0 + r;
        if (node < N_NODES)
            out[(size_t)node * 16 + c] = sO[m0 + r][c] + g_pm[(size_t)node * 16 + c] + sb[c];
    }
}

// ---------------------------------------------------------------------------
extern "C" void kernel_launch(void* const* d_in, const int* in_sizes, int n_in,
                              void* d_out, int out_size) {
    const float* x   = (const float*)d_in[0];
    const int*   ei  = (const int*)d_in[1];     // int32 (JAX x64 disabled)
    const float* W1l = (const float*)d_in[2];
    const float* b1  = (const float*)d_in[3];
    const float* W1r = (const float*)d_in[4];
    const float* W2l = (const float*)d_in[5];
    const float* b2  = (const float*)d_in[6];
    const float* W2r = (const float*)d_in[7];
    float* out = (float*)d_out;

    const int NBLK = (N_NODES + 63) / 64;   // 782

    zero_cnt_k<<<(N_NODES + 255) / 256, 256>>>();
    fill_k<<<(N_EDGES + 255) / 256, 256>>>(ei);
    gather_mean_k<0, 4><<<(N_NODES * 16 + 255) / 256, 256>>>((const float4*)x);
    layer1_k<<<NBLK, 128>>>(x, W1l, b1, W1r, W2l);
    gather_mean_k<1, 2><<<(N_NODES * 4 + 255) / 256, 256>>>(nullptr);
    final_k<<<NBLK, 128>>>(W2r, b2, out);
}